// round 16
// baseline (speedup 1.0000x reference)
#include <cuda_runtime.h>
#include <cuda_bf16.h>
#include <cstdint>

// Problem constants
#define D_MODEL 1024
#define HID     4096
#define N_KEYS  65536
#define TOP_K   6

#define NEG_INF (-3.402823466e38f)
#define CAND_CAP 1024   // candidate buffer capacity
#define FAST_CAP 256    // fast-path limit (expected cnt ~88 at T=3*sigma)

// Scratch (no device allocation; zeroed at module load, re-zeroed by k_topk_mean)
__device__ float g_v[D_MODEL];
__device__ float g_scores[N_KEYS];
__device__ float g_cval[CAND_CAP];
__device__ int   g_cidx[CAND_CAP];
__device__ int   g_cnt;

// ---------------------------------------------------------------------------
__device__ __forceinline__ void warp_argmax(float& v, int& i) {
#pragma unroll
    for (int o = 16; o > 0; o >>= 1) {
        float ov = __shfl_xor_sync(0xFFFFFFFFu, v, o);
        int   oi = __shfl_xor_sync(0xFFFFFFFFu, i, o);
        if (ov > v || (ov == v && oi < i)) { v = ov; i = oi; }
    }
}

__device__ __forceinline__ float4 ldcs4(const float4* p) { return __ldcs(p); }

// ---------------------------------------------------------------------------
// Kernel 1 (fused q+v) — EXACT R5 config (measured 18.75us; best of 5 tried
// geometries: 256x16 fused beat 512x8, 1024x4, and both split variants).
// Block b owns h-rows [16b, 16b+16). Phase 1: 8 warps compute the 16 q values
// (2 rows/warp). Phase 2: 256 threads stream the 16 Wk rows, atomicAdd into
// g_v (256 reductions/address). Requires g_v == 0 on entry.
// ---------------------------------------------------------------------------
__global__ void k_qv(const float* __restrict__ Wq,
                     const float* __restrict__ bq,
                     const float* __restrict__ query,
                     const float* __restrict__ Wk) {
    const int t = threadIdx.x;      // 0..255
    const int warp = t >> 5;        // 0..7
    const int lane = t & 31;
    const int h0 = blockIdx.x * 16;

    __shared__ float sq[16];
    __shared__ float4 squery[D_MODEL / 4];

    squery[t] = reinterpret_cast<const float4*>(query)[t];
    __syncthreads();

    // phase 1: warp w computes q[h0+2w] and q[h0+2w+1]
#pragma unroll
    for (int rr = 0; rr < 2; rr++) {
        const int h = h0 + warp * 2 + rr;
        const float4* w4 = reinterpret_cast<const float4*>(Wq + (size_t)h * D_MODEL);
        float acc = 0.0f;
#pragma unroll
        for (int i = 0; i < 8; i++) {
            float4 a = ldcs4(&w4[lane + 32 * i]);
            float4 b = squery[lane + 32 * i];
            acc += a.x * b.x + a.y * b.y + a.z * b.z + a.w * b.w;
        }
#pragma unroll
        for (int o = 16; o > 0; o >>= 1) acc += __shfl_xor_sync(0xFFFFFFFFu, acc, o);
        if (lane == 0) sq[warp * 2 + rr] = acc + bq[h];
    }
    __syncthreads();

    // phase 2: v partial over these 16 h rows; thread owns float4 column t
    float4 acc = make_float4(0.f, 0.f, 0.f, 0.f);
#pragma unroll
    for (int j = 0; j < 16; j++) {
        float qh = sq[j];
        float4 w = ldcs4(&reinterpret_cast<const float4*>(Wk + (size_t)(h0 + j) * D_MODEL)[t]);
        acc.x += w.x * qh;
        acc.y += w.y * qh;
        acc.z += w.z * qh;
        acc.w += w.w * qh;
    }
    atomicAdd(&g_v[t * 4 + 0], acc.x);
    atomicAdd(&g_v[t * 4 + 1], acc.y);
    atomicAdd(&g_v[t * 4 + 2], acc.z);
    atomicAdd(&g_v[t * 4 + 3], acc.w);
}

// ---------------------------------------------------------------------------
// Kernel 2 — EXACT R5 streaming kernel (do NOT adorn: every added fence /
// epilogue measured -8 to -30us). scores[n] = key_mat[n].v, warp per row,
// plus the statistical threshold filter: scores ~ N(0, ||v||^2) for iid
// N(0,1) keys; T = 3*sigma passes ~88 of 65536 rows.
// ---------------------------------------------------------------------------
__global__ void k_scores(const float* __restrict__ key_mat) {
    __shared__ float4 sv[D_MODEL / 4];
    __shared__ float swsum[8];
    __shared__ float s_T;

    const int t = threadIdx.x;
    const int warp = t >> 5;
    const int lane = t & 31;

    float4 vv = reinterpret_cast<const float4*>(g_v)[t];
    sv[t] = vv;
    float ss = vv.x * vv.x + vv.y * vv.y + vv.z * vv.z + vv.w * vv.w;
#pragma unroll
    for (int o = 16; o > 0; o >>= 1) ss += __shfl_xor_sync(0xFFFFFFFFu, ss, o);
    if (lane == 0) swsum[warp] = ss;
    __syncthreads();
    if (t == 0) {
        float tot = swsum[0] + swsum[1] + swsum[2] + swsum[3]
                  + swsum[4] + swsum[5] + swsum[6] + swsum[7];
        s_T = 3.0f * sqrtf(tot);
    }
    __syncthreads();

    const int row = blockIdx.x * 8 + warp;
    const float4* kr = reinterpret_cast<const float4*>(key_mat + (size_t)row * D_MODEL);

    float acc = 0.0f;
#pragma unroll
    for (int i = 0; i < 8; i++) {
        float4 a = ldcs4(&kr[lane + 32 * i]);
        float4 b = sv[lane + 32 * i];
        acc += a.x * b.x + a.y * b.y + a.z * b.z + a.w * b.w;
    }
#pragma unroll
    for (int o = 16; o > 0; o >>= 1) acc += __shfl_xor_sync(0xFFFFFFFFu, acc, o);
    if (lane == 0) {
        g_scores[row] = acc;   // kept for the exact fallback
        if (acc >= s_T) {
            int slot = atomicAdd(&g_cnt, 1);
            if (slot < CAND_CAP) {
                g_cval[slot] = acc;
                g_cidx[slot] = row;
            }
        }
    }
}

// ---------------------------------------------------------------------------
// Kernel 3 — warp-local fast-path selection (measured 7.7us vs 9.6us for the
// block-barrier version), then out = mean(key_mat[top6]), then scratch reset.
// ---------------------------------------------------------------------------
__global__ void k_topk_mean(const float* __restrict__ key_mat,
                            float* __restrict__ out) {
    const int t = threadIdx.x;   // 0..1023
    const int lane = t & 31;
    const int warp = t >> 5;

    __shared__ float scv[FAST_CAP];
    __shared__ int   sci[FAST_CAP];
    __shared__ int   s_win[TOP_K];

    const int cnt = g_cnt;
    const bool fast = (cnt >= TOP_K && cnt <= FAST_CAP);

    if (fast) {
        if (t < FAST_CAP) {
            scv[t] = (t < cnt) ? g_cval[t] : NEG_INF;
            sci[t] = (t < cnt) ? g_cidx[t] : -1;
        }
        __syncthreads();
        if (t < 32) {
            // warp 0 runs all 6 rounds alone: 8 slots per lane, warp syncs only
#pragma unroll
            for (int r = 0; r < TOP_K; r++) {
                float bv = NEG_INF; int bi = -1; int bs = -1;
#pragma unroll
                for (int j = 0; j < 8; j++) {
                    int slot = t + 32 * j;
                    float v = scv[slot];
                    int   i = sci[slot];
                    if (v > bv || (v == bv && i < bi)) { bv = v; bi = i; bs = slot; }
                }
                float mv = bv; int mi = bi;
                warp_argmax(mv, mi);
                if (bi == mi && bs >= 0) scv[bs] = NEG_INF;  // unique owner
                if (t == 0) s_win[r] = mi;
                __syncwarp();
            }
        }
        __syncthreads();
    } else {
        // exact fallback: full scan over g_scores (effectively never taken;
        // guarantees exactness for any input distribution)
        __shared__ float swv[32];
        __shared__ int   swi[32];
        __shared__ int   s_wi;

        float lv[TOP_K];
        int   li[TOP_K];
#pragma unroll
        for (int j = 0; j < TOP_K; j++) { lv[j] = NEG_INF; li[j] = -1; }
        const float4* s4 = reinterpret_cast<const float4*>(g_scores);
        for (int b = 0; b < 16; b++) {
            int i4 = t + 1024 * b;
            float4 x = s4[i4];
            float vals[4] = {x.x, x.y, x.z, x.w};
#pragma unroll
            for (int c = 0; c < 4; c++) {
                float xv = vals[c];
                if (xv > lv[TOP_K - 1]) {
                    int id = i4 * 4 + c;
                    int j = TOP_K - 1;
                    while (j > 0 && xv > lv[j - 1]) {
                        lv[j] = lv[j - 1]; li[j] = li[j - 1]; j--;
                    }
                    lv[j] = xv; li[j] = id;
                }
            }
        }
        float v = lv[0]; int i = li[0];
        int p = 0;
        for (int r = 0; r < TOP_K; r++) {
            float bv = v; int bi = i;
            warp_argmax(bv, bi);
            if (lane == 0) { swv[warp] = bv; swi[warp] = bi; }
            __syncthreads();
            if (warp == 0) {
                float mv = swv[lane];
                int   mi = swi[lane];
                warp_argmax(mv, mi);
                if (lane == 0) { s_wi = mi; s_win[r] = mi; }
            }
            __syncthreads();
            if (i == s_wi) {
                p++;
                v = (p < TOP_K) ? lv[p] : NEG_INF;
                i = (p < TOP_K) ? li[p] : -1;
            }
            __syncthreads();
        }
    }

    // mean of the 6 selected rows (t indexes the 1024 output elements)
    float s = 0.0f;
#pragma unroll
    for (int j = 0; j < TOP_K; j++) {
        s += key_mat[(size_t)s_win[j] * D_MODEL + t];
    }
    out[t] = s * (1.0f / 6.0f);

    // reset scratch so the next graph replay starts from identical state
    g_v[t] = 0.0f;
    if (t == 0) g_cnt = 0;
}

// ---------------------------------------------------------------------------
extern "C" void kernel_launch(void* const* d_in, const int* in_sizes, int n_in,
                              void* d_out, int out_size) {
    const float* query   = (const float*)d_in[0];  // [1024]
    const float* key_mat = (const float*)d_in[1];  // [65536, 1024]
    const float* Wq      = (const float*)d_in[2];  // [4096, 1024]
    const float* bq      = (const float*)d_in[3];  // [4096]
    const float* Wk      = (const float*)d_in[4];  // [4096, 1024]
    // d_in[5] = bk: constant shift of all scores -> top-k indices unchanged
    float* out = (float*)d_out;                    // [1024] f32

    k_qv<<<256, 256>>>(Wq, bq, query, Wk);     // fused q + v partials (R5)
    k_scores<<<N_KEYS / 8, 256>>>(key_mat);    // stream + threshold filter (R5)
    k_topk_mean<<<1, 1024>>>(key_mat, out);    // warp-local top-6 + mean
}